// round 11
// baseline (speedup 1.0000x reference)
#include <cuda_runtime.h>
#include <math.h>

#define NPTS 262144
#define NLVL 16
#define TSZ  (1u << 19)
#define TMASK (TSZ - 1u)

typedef unsigned long long u64t;

__device__ __forceinline__ u64t pk2(float a, float b) {
    u64t r; asm("mov.b64 %0,{%1,%2};" : "=l"(r) : "f"(a), "f"(b)); return r;
}
__device__ __forceinline__ void upk2(u64t v, float& a, float& b) {
    asm("mov.b64 {%0,%1},%2;" : "=f"(a), "=f"(b) : "l"(v));
}
__device__ __forceinline__ void fma2(u64t& d, u64t a, u64t b) {
    asm("fma.rn.f32x2 %0,%1,%2,%0;" : "+l"(d) : "l"(a), "l"(b));
}

// ---------------------------------------------------------------------------
constexpr int OFF_SW0 = 0;            // 32*64
constexpr int OFF_SW1 = 2048;         // 64*64
constexpr int OFF_SW2 = 6144;         // 64*16
constexpr int OFF_CW0 = 7168;         // 42*64
constexpr int OFF_CW1 = 9856;         // 64*64
constexpr int OFF_CW2 = 13952;        // 64*3
constexpr int W_TOTAL = 14144;
__constant__ float c_w[W_TOTAL];

__constant__ int c_res[NLVL] = {16, 20, 25, 32, 40, 50, 64, 80,
                                101, 128, 161, 203, 256, 322, 406, 512};

constexpr int BP = 128;
constexpr int NT = 512;               // threads per CTA
constexpr int S  = 132;
constexpr int OFF_B0 = 0;
constexpr int OFF_B1 = 64 * S;
constexpr int SMEM_FLOATS = 2 * 64 * S;          // 16896
constexpr int SMEM_BYTES  = SMEM_FLOATS * 4;     // 67584

// ---------------------------------------------------------------------------
// GEMM: y[64][S] = act(W[IN][64]^T x[IN][S]).
// warp -> 8 neurons x 64 points (pg = warp>>3 picks point half).
// lane -> 2 points (LDS.64); weights = natural 64-bit pairs via 2x LDC.128.
// acc[neuron-pair][point]. Per iter: 1 LDS.64 + 2 MOV + 2 LDC.128 + 8 FFMA2.
// ---------------------------------------------------------------------------
template <int IN, bool RELU>
__device__ __forceinline__ void gemmN(const float* __restrict__ xb,
                                      float* __restrict__ yb,
                                      int woff, int warp, int lane)
{
    const int pg = warp >> 3;          // point half: 0 or 1
    const int nw = warp & 7;           // neuron group: 8 neurons
    u64t acc[4][2];
    #pragma unroll
    for (int n = 0; n < 4; n++) { acc[n][0] = 0ull; acc[n][1] = 0ull; }

    const float* xr = xb + pg * 64 + lane * 2;
    const float* wr = c_w + woff + nw * 8;
    #pragma unroll 8
    for (int i = 0; i < IN; i++) {
        float2 xv = *(const float2*)(xr + i * S);
        u64t x0 = pk2(xv.x, xv.x);
        u64t x1 = pk2(xv.y, xv.y);
        ulonglong2 wa = *(const ulonglong2*)(wr + i * 64);
        ulonglong2 wb = *(const ulonglong2*)(wr + i * 64 + 4);
        fma2(acc[0][0], x0, wa.x); fma2(acc[0][1], x1, wa.x);
        fma2(acc[1][0], x0, wa.y); fma2(acc[1][1], x1, wa.y);
        fma2(acc[2][0], x0, wb.x); fma2(acc[2][1], x1, wb.x);
        fma2(acc[3][0], x0, wb.y); fma2(acc[3][1], x1, wb.y);
    }
    #pragma unroll
    for (int n = 0; n < 4; n++) {
        float lo0, hi0, lo1, hi1;
        upk2(acc[n][0], lo0, hi0);     // point0: neurons (2n, 2n+1)
        upk2(acc[n][1], lo1, hi1);     // point1
        if (RELU) {
            lo0 = fmaxf(lo0, 0.f); lo1 = fmaxf(lo1, 0.f);
            hi0 = fmaxf(hi0, 0.f); hi1 = fmaxf(hi1, 0.f);
        }
        *(float2*)(yb + (nw * 8 + 2 * n + 0) * S + pg * 64 + lane * 2) =
            make_float2(lo0, lo1);
        *(float2*)(yb + (nw * 8 + 2 * n + 1) * S + pg * 64 + lane * 2) =
            make_float2(hi0, hi1);
    }
}

// sw2 GEMM (64 -> 16): warp -> 1 neuron pair x 64 points
__device__ __forceinline__ void gemm16N(const float* __restrict__ xb,
                                        float* __restrict__ yb,
                                        int warp, int lane)
{
    const int pg = warp >> 3;
    const int nw = warp & 7;           // neuron pair nw -> neurons 2nw, 2nw+1
    u64t acc0 = 0ull, acc1 = 0ull;

    const float* xr = xb + pg * 64 + lane * 2;
    const float* wr = c_w + OFF_SW2 + nw * 2;
    #pragma unroll 8
    for (int i = 0; i < 64; i++) {
        float2 xv = *(const float2*)(xr + i * S);
        u64t wp = *(const u64t*)(wr + i * 16);       // natural pair
        fma2(acc0, pk2(xv.x, xv.x), wp);
        fma2(acc1, pk2(xv.y, xv.y), wp);
    }
    float lo0, hi0, lo1, hi1;
    upk2(acc0, lo0, hi0);
    upk2(acc1, lo1, hi1);
    *(float2*)(yb + (nw * 2 + 0) * S + pg * 64 + lane * 2) =
        make_float2(lo0, lo1);
    *(float2*)(yb + (nw * 2 + 1) * S + pg * 64 + lane * 2) =
        make_float2(hi0, hi1);
}

// ---------------------------------------------------------------------------
// Fused kernel: hash encode (-> smem) then MLPs. 128 points / block, 512 thr.
// ---------------------------------------------------------------------------
__global__ __launch_bounds__(NT, 2) void fused_kernel(
    const float* __restrict__ xyzt,
    const float* __restrict__ dirs,
    const float* __restrict__ table,
    float* __restrict__ out)
{
    extern __shared__ float s[];
    const int tid = threadIdx.x;
    const int warp = tid >> 5, lane = tid & 31;
    const int gbase = blockIdx.x * BP;

    // ---- stage xyzt into B1 (512 floats) ----
    if (tid < 512)
        s[OFF_B1 + tid] = xyzt[(size_t)gbase * 4 + tid];
    __syncthreads();

    // ---- hash phase: 4 threads per point, 4 levels each (R10-validated) ----
    {
        const int p = tid & 127;
        const int lh = tid >> 7;                     // 0..3 (warp-uniform)
        float4 pt = *(const float4*)(s + OFF_B1 + p * 4);

        #pragma unroll 1
        for (int k = 0; k < 4; k++) {
            const int l = 4 * k + lh;
            float r = (float)c_res[l];
            float px = pt.x * r, py = pt.y * r, pz = pt.z * r, pw = pt.w * r;
            float fx = floorf(px), fy = floorf(py), fz = floorf(pz), ft = floorf(pw);
            float wx = px - fx, wy = py - fy, wz = pz - fz, wt = pw - ft;
            unsigned cx = (unsigned)fx, cy = (unsigned)fy,
                     cz = (unsigned)fz, ct = (unsigned)ft;

            unsigned hx0 = cx,               hx1 = cx + 1u;
            unsigned hy0 = cy * 2654435761u, hy1 = (cy + 1u) * 2654435761u;
            unsigned hz0 = cz * 805459861u,  hz1 = (cz + 1u) * 805459861u;
            unsigned ht0 = ct * 3674653429u, ht1 = (ct + 1u) * 3674653429u;

            float wx0 = 1.f - wx, wy0 = 1.f - wy, wz0 = 1.f - wz, wt0 = 1.f - wt;

            const float2* tl = (const float2*)table + (size_t)l * TSZ;
            float a0 = 0.f, a1 = 0.f;

            if ((cx & 1u) == 0u) {
                const float4* t4 = (const float4*)tl;
                #pragma unroll
                for (int c8 = 0; c8 < 8; c8++) {
                    unsigned hyy = (c8 & 1) ? hy1 : hy0;
                    unsigned hzz = (c8 & 2) ? hz1 : hz0;
                    unsigned htt = (c8 & 4) ? ht1 : ht0;
                    unsigned idx0 = (hx0 ^ hyy ^ hzz ^ htt) & TMASK;
                    float wyzt = ((c8 & 1) ? wy : wy0) * ((c8 & 2) ? wz : wz0) *
                                 ((c8 & 4) ? wt : wt0);
                    float w0 = wx0 * wyzt, w1 = wx * wyzt;
                    float4 v = __ldg(&t4[idx0 >> 1]);
                    bool hi = (idx0 & 1u);
                    float f0x = hi ? v.z : v.x, f0y = hi ? v.w : v.y;
                    float f1x = hi ? v.x : v.z, f1y = hi ? v.y : v.w;
                    a0 = fmaf(f0x, w0, a0); a0 = fmaf(f1x, w1, a0);
                    a1 = fmaf(f0y, w0, a1); a1 = fmaf(f1y, w1, a1);
                }
            } else {
                #pragma unroll
                for (int c8 = 0; c8 < 16; c8++) {
                    unsigned hxx = (c8 & 1) ? hx1 : hx0;
                    unsigned hyy = (c8 & 2) ? hy1 : hy0;
                    unsigned hzz = (c8 & 4) ? hz1 : hz0;
                    unsigned htt = (c8 & 8) ? ht1 : ht0;
                    unsigned idx = (hxx ^ hyy ^ hzz ^ htt) & TMASK;
                    float w = ((c8 & 1) ? wx : wx0) * ((c8 & 2) ? wy : wy0) *
                              ((c8 & 4) ? wz : wz0) * ((c8 & 8) ? wt : wt0);
                    float2 f = __ldg(&tl[idx]);
                    a0 = fmaf(f.x, w, a0);
                    a1 = fmaf(f.y, w, a1);
                }
            }
            s[OFF_B0 + (2 * l + 0) * S + p] = a0;
            s[OFF_B0 + (2 * l + 1) * S + p] = a1;
        }
    }
    __syncthreads();

    // ---- sigma net ----
    gemmN<32, true>(s + OFF_B0, s + OFF_B1, OFF_SW0, warp, lane);
    __syncthreads();
    gemmN<64, true>(s + OFF_B1, s + OFF_B0, OFF_SW1, warp, lane);
    __syncthreads();
    gemm16N(s + OFF_B0, s + OFF_B1, warp, lane);       // h -> B1 rows 0..15
    __syncthreads();

    // ---- color input assembly + sigma output ----
    if (tid < BP) {
        const int p = tid;
        const int gn = gbase + p;
        float d0 = dirs[(size_t)gn * 3 + 0];
        float d1 = dirs[(size_t)gn * 3 + 1];
        float d2 = dirs[(size_t)gn * 3 + 2];
        s[OFF_B0 + 0 * S + p] = d0;
        s[OFF_B0 + 1 * S + p] = d1;
        s[OFF_B0 + 2 * S + p] = d2;
        float dd[3] = {d0, d1, d2};
        #pragma unroll
        for (int f = 0; f < 4; f++) {
            float fr = (float)(1 << f);
            #pragma unroll
            for (int c = 0; c < 3; c++) {
                float ang = dd[c] * fr;
                s[OFF_B0 + (3 + f * 3 + c) * S + p]  = __sinf(ang);
                s[OFF_B0 + (15 + f * 3 + c) * S + p] = __cosf(ang);
            }
        }
        #pragma unroll
        for (int k = 0; k < 15; k++)
            s[OFF_B0 + (27 + k) * S + p] = s[OFF_B1 + (1 + k) * S + p];
        out[gn] = s[OFF_B1 + 0 * S + p];               // sigma
    }
    __syncthreads();

    // ---- color net ----
    gemmN<42, true>(s + OFF_B0, s + OFF_B1, OFF_CW0, warp, lane);
    __syncthreads();
    gemmN<64, true>(s + OFF_B1, s + OFF_B0, OFF_CW1, warp, lane);
    __syncthreads();

    // ---- final 64 -> 3 + sigmoid ----
    if (tid < BP) {
        const int p = tid;
        const int gn = gbase + p;
        float r0 = 0.f, r1 = 0.f, r2 = 0.f;
        #pragma unroll 8
        for (int i = 0; i < 64; i++) {
            float xv = s[OFF_B0 + i * S + p];
            r0 = fmaf(xv, c_w[OFF_CW2 + i * 3 + 0], r0);
            r1 = fmaf(xv, c_w[OFF_CW2 + i * 3 + 1], r1);
            r2 = fmaf(xv, c_w[OFF_CW2 + i * 3 + 2], r2);
        }
        out[(size_t)NPTS + (size_t)gn * 3 + 0] = 1.f / (1.f + __expf(-r0));
        out[(size_t)NPTS + (size_t)gn * 3 + 1] = 1.f / (1.f + __expf(-r1));
        out[(size_t)NPTS + (size_t)gn * 3 + 2] = 1.f / (1.f + __expf(-r2));
    }
}

// ---------------------------------------------------------------------------
extern "C" void kernel_launch(void* const* d_in, const int* in_sizes, int n_in,
                              void* d_out, int out_size)
{
    const float* xyzt  = (const float*)d_in[0];
    const float* dirs  = (const float*)d_in[1];
    const float* table = (const float*)d_in[2];

    cudaMemcpyToSymbolAsync(c_w, d_in[3], 2048 * 4, OFF_SW0 * 4,
                            cudaMemcpyDeviceToDevice);
    cudaMemcpyToSymbolAsync(c_w, d_in[4], 4096 * 4, OFF_SW1 * 4,
                            cudaMemcpyDeviceToDevice);
    cudaMemcpyToSymbolAsync(c_w, d_in[5], 1024 * 4, OFF_SW2 * 4,
                            cudaMemcpyDeviceToDevice);
    cudaMemcpyToSymbolAsync(c_w, d_in[6], 2688 * 4, OFF_CW0 * 4,
                            cudaMemcpyDeviceToDevice);
    cudaMemcpyToSymbolAsync(c_w, d_in[7], 4096 * 4, OFF_CW1 * 4,
                            cudaMemcpyDeviceToDevice);
    cudaMemcpyToSymbolAsync(c_w, d_in[8], 192 * 4, OFF_CW2 * 4,
                            cudaMemcpyDeviceToDevice);

    cudaFuncSetAttribute(fused_kernel, cudaFuncAttributeMaxDynamicSharedMemorySize,
                         SMEM_BYTES);

    fused_kernel<<<NPTS / BP, NT, SMEM_BYTES>>>(xyzt, dirs, table, (float*)d_out);
}